// round 8
// baseline (speedup 1.0000x reference)
#include <cuda_runtime.h>
#include <cuda_fp16.h>

#define NN    100000
#define EE    1600000
#define NADJ  4
#define DD    64
#define SLACK 64                      // bucket slots per row; P(deg>64)~1e-19

#define BUILD_BLKX ((EE + 255) / 256) // 6250
#define GEMM_BLKS  ((NN + 63) / 64)   // 1563

// ---------------- device scratch (static globals; no allocs allowed) ------
__device__ __align__(16) __half2 g_h [(size_t)NN * 32];   // s0 (fp16 storage)
__device__ __align__(16) __half2 g_s1[(size_t)NN * 32];   // s1 (fp16 storage)
__device__ __align__(16) float2  g_edges[(size_t)NADJ * NN * SLACK]; // bucketed
__device__ int g_cnt[NADJ * NN];

// used-adjacency predicate (6 cached loads)
__device__ __forceinline__ bool adj_used(int a, const int* __restrict__ iq,
                                         const int* __restrict__ ir) {
    return __ldg(iq + 0) == a || __ldg(iq + 1) == a ||
           __ldg(iq + 2) == a || __ldg(iq + 3) == a ||
           __ldg(ir + 0) == a || __ldg(ir + 1) == a;
}

__global__ void zero_cnt_kernel() {
    int i = blockIdx.x * blockDim.x + threadIdx.x;
    if (i < NADJ * NN) g_cnt[i] = 0;
}

// ---------------- fused bucket-build + GEMM ---------------------------------
// blockIdx.y in [0, NADJ): single-pass edge bucketing for adjacency y.
//   Edge record stores PRESCALED col byte-offset (c<<7) for cheap gather addr.
// blockIdx.y == NADJ:      GEMM h = x@W + b.
__global__ void build_gemm_kernel(const int* __restrict__ rows,
                                  const int* __restrict__ cols,
                                  const float* __restrict__ vals,
                                  const float* __restrict__ x,
                                  const float* __restrict__ Wm,
                                  const float* __restrict__ b,
                                  const int* __restrict__ iq,
                                  const int* __restrict__ ir) {
    __shared__ float4 Ws4[64 * 16];
    __shared__ float  Xs[64 * 65];
    int tid = threadIdx.x;

    if (blockIdx.y < NADJ) {
        int a = blockIdx.y;
        if (!adj_used(a, iq, ir)) return;
        int e = blockIdx.x * blockDim.x + tid;
        if (e < EE) {
            size_t idx = (size_t)a * EE + e;
            int   r = rows[idx];
            int   c = cols[idx];
            float v = vals[idx];
            int   p = atomicAdd(&g_cnt[a * NN + r], 1);
            p = min(p, SLACK - 1);   // structurally unreachable; guards memory
            g_edges[((size_t)a * NN + r) * SLACK + p] =
                make_float2(__int_as_float(c << 7), v);   // byte offset of row
        }
        return;
    }

    // ---- GEMM part ----
    if (blockIdx.x >= GEMM_BLKS) return;
    for (int i = tid; i < 64 * 16; i += 256) Ws4[i] = ((const float4*)Wm)[i];
    int rowBase = blockIdx.x * 64;
    for (int i = tid; i < 1024; i += 256) {
        int r = i >> 4, c4 = i & 15;
        int grow = rowBase + r;
        float4 v = make_float4(0.f, 0.f, 0.f, 0.f);
        if (grow < NN) v = ((const float4*)x)[(size_t)grow * 16 + c4];
        int o = r * 65 + c4 * 4;
        Xs[o] = v.x; Xs[o + 1] = v.y; Xs[o + 2] = v.z; Xs[o + 3] = v.w;
    }
    __syncthreads();
    int tx = tid & 15, ty = tid >> 4;
    float4 a0 = make_float4(0.f,0.f,0.f,0.f), a1 = a0, a2 = a0, a3 = a0;
    #pragma unroll 8
    for (int k = 0; k < 64; k++) {
        float4 wv = Ws4[k * 16 + tx];
        float x0 = Xs[(ty * 4 + 0) * 65 + k];
        float x1 = Xs[(ty * 4 + 1) * 65 + k];
        float x2 = Xs[(ty * 4 + 2) * 65 + k];
        float x3 = Xs[(ty * 4 + 3) * 65 + k];
        a0.x += x0 * wv.x; a0.y += x0 * wv.y; a0.z += x0 * wv.z; a0.w += x0 * wv.w;
        a1.x += x1 * wv.x; a1.y += x1 * wv.y; a1.z += x1 * wv.z; a1.w += x1 * wv.w;
        a2.x += x2 * wv.x; a2.y += x2 * wv.y; a2.z += x2 * wv.z; a2.w += x2 * wv.w;
        a3.x += x3 * wv.x; a3.y += x3 * wv.y; a3.z += x3 * wv.z; a3.w += x3 * wv.w;
    }
    float4 bv = ((const float4*)b)[tx];
    float4 outs[4] = {a0, a1, a2, a3};
    int r0 = rowBase + ty * 4;
    #pragma unroll
    for (int i = 0; i < 4; i++) {
        int r = r0 + i;
        if (r < NN) {
            float4 o = outs[i];
            o.x += bv.x; o.y += bv.y; o.z += bv.z; o.w += bv.w;
            __half2 p0 = __floats2half2_rn(o.x, o.y);
            __half2 p1 = __floats2half2_rn(o.z, o.w);
            __half2 pk[2] = {p0, p1};
            ((uint2*)g_h)[(size_t)r * 16 + tx] = *(uint2*)pk;
        }
    }
}

// ---------------- gather SpMM core ------------------------------------------
// Warp owns one output row; lane l accumulates columns 2l, 2l+1 (one half2).
// Edge records carry prescaled byte offsets; 8x unroll, loads front-batched.
__device__ __forceinline__ void accum_lists(int a, int r,
                                            const __half2* __restrict__ src,
                                            unsigned lane4, float& ax, float& ay) {
    const float4* __restrict__ ed4 =
        (const float4*)(g_edges + ((size_t)a * NN + r) * SLACK);
    const char* __restrict__ base = (const char*)src + lane4;
    int end = min(__ldg(&g_cnt[a * NN + r]), SLACK);
    int i = 0;
    for (; i + 8 <= end; i += 8) {
        float4 p0 = ed4[(i >> 1) + 0];
        float4 p1 = ed4[(i >> 1) + 1];
        float4 p2 = ed4[(i >> 1) + 2];
        float4 p3 = ed4[(i >> 1) + 3];
        __half2 h0 = __ldg((const __half2*)(base + (unsigned)__float_as_int(p0.x)));
        __half2 h1 = __ldg((const __half2*)(base + (unsigned)__float_as_int(p0.z)));
        __half2 h2 = __ldg((const __half2*)(base + (unsigned)__float_as_int(p1.x)));
        __half2 h3 = __ldg((const __half2*)(base + (unsigned)__float_as_int(p1.z)));
        __half2 h4 = __ldg((const __half2*)(base + (unsigned)__float_as_int(p2.x)));
        __half2 h5 = __ldg((const __half2*)(base + (unsigned)__float_as_int(p2.z)));
        __half2 h6 = __ldg((const __half2*)(base + (unsigned)__float_as_int(p3.x)));
        __half2 h7 = __ldg((const __half2*)(base + (unsigned)__float_as_int(p3.z)));
        float2 f0 = __half22float2(h0), f1 = __half22float2(h1);
        float2 f2 = __half22float2(h2), f3 = __half22float2(h3);
        float2 f4 = __half22float2(h4), f5 = __half22float2(h5);
        float2 f6 = __half22float2(h6), f7 = __half22float2(h7);
        ax += p0.y * f0.x; ay += p0.y * f0.y;
        ax += p0.w * f1.x; ay += p0.w * f1.y;
        ax += p1.y * f2.x; ay += p1.y * f2.y;
        ax += p1.w * f3.x; ay += p1.w * f3.y;
        ax += p2.y * f4.x; ay += p2.y * f4.y;
        ax += p2.w * f5.x; ay += p2.w * f5.y;
        ax += p3.y * f6.x; ay += p3.y * f6.y;
        ax += p3.w * f7.x; ay += p3.w * f7.y;
    }
    const float2* __restrict__ ed = (const float2*)ed4;
    for (; i < end; i++) {
        float2 e = ed[i];
        float2 hv = __half22float2(
            __ldg((const __half2*)(base + (unsigned)__float_as_int(e.x))));
        ax += e.y * hv.x; ay += e.y * hv.y;
    }
}

// op(src) = (spmm(a0,src)+spmm(a1,src))/2 ; if a0==a1 this equals spmm(a0,src)
__device__ __forceinline__ void op_pair(int a0, int a1, int r,
                                        const __half2* __restrict__ src,
                                        unsigned lane4, float& ox, float& oy) {
    float ax = 0.f, ay = 0.f;
    accum_lists(a0, r, src, lane4, ax, ay);
    if (a0 != a1) {
        accum_lists(a1, r, src, lane4, ax, ay);
        ax *= 0.5f; ay *= 0.5f;
    }
    ox += ax; oy += ay;
}

// s1 = op_seq0(h)
__global__ void spmm_mid_kernel(const int* __restrict__ idxes_seq) {
    int w    = (blockIdx.x * blockDim.x + threadIdx.x) >> 5;
    int lane = threadIdx.x & 31;
    if (w >= NN) return;
    unsigned lane4 = (unsigned)lane << 2;
    float ax = 0.f, ay = 0.f;
    op_pair(__ldg(idxes_seq + 0), __ldg(idxes_seq + 1), w, g_h, lane4, ax, ay);
    g_s1[(size_t)w * 32 + lane] = __floats2half2_rn(ax, ay);
}

// s2 = op_seq1(s1) + op_res(h); LN; exact GELU
__global__ void final_kernel(const int* __restrict__ idxes_seq,
                             const int* __restrict__ idxes_res,
                             const float* __restrict__ gamma,
                             const float* __restrict__ beta,
                             float* __restrict__ out) {
    int w    = (blockIdx.x * blockDim.x + threadIdx.x) >> 5;
    int lane = threadIdx.x & 31;
    if (w >= NN) return;
    unsigned lane4 = (unsigned)lane << 2;
    float ax = 0.f, ay = 0.f;
    op_pair(__ldg(idxes_seq + 2), __ldg(idxes_seq + 3), w, g_s1, lane4, ax, ay);
    op_pair(__ldg(idxes_res + 0), __ldg(idxes_res + 1), w, g_h,  lane4, ax, ay);

    float s  = ax + ay;
    float ss = ax * ax + ay * ay;
    #pragma unroll
    for (int d = 16; d; d >>= 1) {
        s  += __shfl_xor_sync(0xffffffffu, s,  d);
        ss += __shfl_xor_sync(0xffffffffu, ss, d);
    }
    float mu   = s * (1.0f / 64.0f);
    float var  = ss * (1.0f / 64.0f) - mu * mu;
    float rstd = rsqrtf(var + 1e-5f);

    float2 g2 = ((const float2*)gamma)[lane];
    float2 b2 = ((const float2*)beta)[lane];
    float y0 = (ax - mu) * rstd * g2.x + b2.x;
    float y1 = (ay - mu) * rstd * g2.y + b2.y;
    y0 = 0.5f * y0 * (1.0f + erff(y0 * 0.70710678118654752f));
    y1 = 0.5f * y1 * (1.0f + erff(y1 * 0.70710678118654752f));
    ((float2*)out)[(size_t)w * 32 + lane] = make_float2(y0, y1);
}

// ---------------- launch -----------------------------------------------------
extern "C" void kernel_launch(void* const* d_in, const int* in_sizes, int n_in,
                              void* d_out, int out_size) {
    const float* x         = (const float*)d_in[0];
    const float* W         = (const float*)d_in[1];
    const float* b         = (const float*)d_in[2];
    const int*   rows      = (const int*)  d_in[3];
    const int*   cols      = (const int*)  d_in[4];
    const float* vals      = (const float*)d_in[5];
    const float* gamma     = (const float*)d_in[6];
    const float* beta      = (const float*)d_in[7];
    const int*   idxes_seq = (const int*)  d_in[8];
    const int*   idxes_res = (const int*)  d_in[9];
    float*       out       = (float*)d_out;

    zero_cnt_kernel<<<(NADJ * NN + 255) / 256, 256>>>();
    build_gemm_kernel<<<dim3(BUILD_BLKX, NADJ + 1), 256>>>(
        rows, cols, vals, x, W, b, idxes_seq, idxes_res);
    spmm_mid_kernel<<<(NN + 7) / 8, 256>>>(idxes_seq);
    final_kernel<<<(NN + 7) / 8, 256>>>(idxes_seq, idxes_res, gamma, beta, out);
}

// round 9
// speedup vs baseline: 1.0375x; 1.0375x over previous
#include <cuda_runtime.h>
#include <cuda_fp16.h>

#define NN    100000
#define EE    1600000
#define NADJ  4
#define DD    64
#define SLACK 64                      // bucket slots per row; P(deg>64)~1e-19

#define BUILD_BLKX ((EE + 255) / 256) // 6250
#define GEMM_BLKS  ((NN + 63) / 64)   // 1563

// ---------------- device scratch (static globals; no allocs allowed) ------
__device__ __align__(16) __half2 g_h [(size_t)NN * 32];   // s0 (fp16 storage)
__device__ __align__(16) __half2 g_s1[(size_t)NN * 32];   // s1 (fp16 storage)
__device__ __align__(16) float2  g_edges[(size_t)NADJ * NN * SLACK]; // bucketed
__device__ int g_cnt[NADJ * NN];

// used-adjacency predicate (6 cached loads)
__device__ __forceinline__ bool adj_used(int a, const int* __restrict__ iq,
                                         const int* __restrict__ ir) {
    return __ldg(iq + 0) == a || __ldg(iq + 1) == a ||
           __ldg(iq + 2) == a || __ldg(iq + 3) == a ||
           __ldg(ir + 0) == a || __ldg(ir + 1) == a;
}

__global__ void zero_cnt_kernel() {
    int i = blockIdx.x * blockDim.x + threadIdx.x;
    if (i < NADJ * NN) g_cnt[i] = 0;
}

// ---------------- fused bucket-build + GEMM ---------------------------------
// blockIdx.y in [0, NADJ): single-pass edge bucketing for adjacency y.
//   Edge record stores PRESCALED col byte-offset (c<<7) for cheap gather addr.
// blockIdx.y == NADJ:      GEMM h = x@W + b.
__global__ void build_gemm_kernel(const int* __restrict__ rows,
                                  const int* __restrict__ cols,
                                  const float* __restrict__ vals,
                                  const float* __restrict__ x,
                                  const float* __restrict__ Wm,
                                  const float* __restrict__ b,
                                  const int* __restrict__ iq,
                                  const int* __restrict__ ir) {
    __shared__ float4 Ws4[64 * 16];
    __shared__ float  Xs[64 * 65];
    int tid = threadIdx.x;

    if (blockIdx.y < NADJ) {
        int a = blockIdx.y;
        if (!adj_used(a, iq, ir)) return;
        int e = blockIdx.x * blockDim.x + tid;
        if (e < EE) {
            size_t idx = (size_t)a * EE + e;
            int   r = rows[idx];
            int   c = cols[idx];
            float v = vals[idx];
            int   p = atomicAdd(&g_cnt[a * NN + r], 1);
            p = min(p, SLACK - 1);   // structurally unreachable; guards memory
            g_edges[((size_t)a * NN + r) * SLACK + p] =
                make_float2(__int_as_float(c << 7), v);   // byte offset of row
        }
        return;
    }

    // ---- GEMM part ----
    if (blockIdx.x >= GEMM_BLKS) return;
    for (int i = tid; i < 64 * 16; i += 256) Ws4[i] = ((const float4*)Wm)[i];
    int rowBase = blockIdx.x * 64;
    for (int i = tid; i < 1024; i += 256) {
        int r = i >> 4, c4 = i & 15;
        int grow = rowBase + r;
        float4 v = make_float4(0.f, 0.f, 0.f, 0.f);
        if (grow < NN) v = ((const float4*)x)[(size_t)grow * 16 + c4];
        int o = r * 65 + c4 * 4;
        Xs[o] = v.x; Xs[o + 1] = v.y; Xs[o + 2] = v.z; Xs[o + 3] = v.w;
    }
    __syncthreads();
    int tx = tid & 15, ty = tid >> 4;
    float4 a0 = make_float4(0.f,0.f,0.f,0.f), a1 = a0, a2 = a0, a3 = a0;
    #pragma unroll 8
    for (int k = 0; k < 64; k++) {
        float4 wv = Ws4[k * 16 + tx];
        float x0 = Xs[(ty * 4 + 0) * 65 + k];
        float x1 = Xs[(ty * 4 + 1) * 65 + k];
        float x2 = Xs[(ty * 4 + 2) * 65 + k];
        float x3 = Xs[(ty * 4 + 3) * 65 + k];
        a0.x += x0 * wv.x; a0.y += x0 * wv.y; a0.z += x0 * wv.z; a0.w += x0 * wv.w;
        a1.x += x1 * wv.x; a1.y += x1 * wv.y; a1.z += x1 * wv.z; a1.w += x1 * wv.w;
        a2.x += x2 * wv.x; a2.y += x2 * wv.y; a2.z += x2 * wv.z; a2.w += x2 * wv.w;
        a3.x += x3 * wv.x; a3.y += x3 * wv.y; a3.z += x3 * wv.z; a3.w += x3 * wv.w;
    }
    float4 bv = ((const float4*)b)[tx];
    float4 outs[4] = {a0, a1, a2, a3};
    int r0 = rowBase + ty * 4;
    #pragma unroll
    for (int i = 0; i < 4; i++) {
        int r = r0 + i;
        if (r < NN) {
            float4 o = outs[i];
            o.x += bv.x; o.y += bv.y; o.z += bv.z; o.w += bv.w;
            __half2 p0 = __floats2half2_rn(o.x, o.y);
            __half2 p1 = __floats2half2_rn(o.z, o.w);
            __half2 pk[2] = {p0, p1};
            ((uint2*)g_h)[(size_t)r * 16 + tx] = *(uint2*)pk;
        }
    }
}

// ---------------- gather SpMM core ------------------------------------------
// Warp owns one output row; lane l accumulates columns 2l, 2l+1 (one half2).
// R7 loop shape (4x unroll, float2 edge loads) + prescaled byte offsets.
__device__ __forceinline__ void accum_lists(int a, int r,
                                            const __half2* __restrict__ src,
                                            unsigned lane4, float& ax, float& ay) {
    const float2* __restrict__ ed = g_edges + ((size_t)a * NN + r) * SLACK;
    const char* __restrict__ base = (const char*)src + lane4;
    int end = min(__ldg(&g_cnt[a * NN + r]), SLACK);
    int i = 0;
    for (; i + 4 <= end; i += 4) {
        float2 e0 = ed[i], e1 = ed[i + 1], e2 = ed[i + 2], e3 = ed[i + 3];
        float2 f0 = __half22float2(__ldg((const __half2*)(base + (unsigned)__float_as_int(e0.x))));
        float2 f1 = __half22float2(__ldg((const __half2*)(base + (unsigned)__float_as_int(e1.x))));
        float2 f2 = __half22float2(__ldg((const __half2*)(base + (unsigned)__float_as_int(e2.x))));
        float2 f3 = __half22float2(__ldg((const __half2*)(base + (unsigned)__float_as_int(e3.x))));
        ax += e0.y * f0.x; ay += e0.y * f0.y;
        ax += e1.y * f1.x; ay += e1.y * f1.y;
        ax += e2.y * f2.x; ay += e2.y * f2.y;
        ax += e3.y * f3.x; ay += e3.y * f3.y;
    }
    for (; i < end; i++) {
        float2 e = ed[i];
        float2 hv = __half22float2(
            __ldg((const __half2*)(base + (unsigned)__float_as_int(e.x))));
        ax += e.y * hv.x; ay += e.y * hv.y;
    }
}

// op(src) = (spmm(a0,src)+spmm(a1,src))/2 ; if a0==a1 this equals spmm(a0,src)
__device__ __forceinline__ void op_pair(int a0, int a1, int r,
                                        const __half2* __restrict__ src,
                                        unsigned lane4, float& ox, float& oy) {
    float ax = 0.f, ay = 0.f;
    accum_lists(a0, r, src, lane4, ax, ay);
    if (a0 != a1) {
        accum_lists(a1, r, src, lane4, ax, ay);
        ax *= 0.5f; ay *= 0.5f;
    }
    ox += ax; oy += ay;
}

// s1 = op_seq0(h)
__global__ void __launch_bounds__(256, 8)
spmm_mid_kernel(const int* __restrict__ idxes_seq) {
    int w    = (blockIdx.x * blockDim.x + threadIdx.x) >> 5;
    int lane = threadIdx.x & 31;
    if (w >= NN) return;
    unsigned lane4 = (unsigned)lane << 2;
    float ax = 0.f, ay = 0.f;
    op_pair(__ldg(idxes_seq + 0), __ldg(idxes_seq + 1), w, g_h, lane4, ax, ay);
    g_s1[(size_t)w * 32 + lane] = __floats2half2_rn(ax, ay);
}

// s2 = op_seq1(s1) + op_res(h); LN; exact GELU
__global__ void __launch_bounds__(256, 8)
final_kernel(const int* __restrict__ idxes_seq,
             const int* __restrict__ idxes_res,
             const float* __restrict__ gamma,
             const float* __restrict__ beta,
             float* __restrict__ out) {
    int w    = (blockIdx.x * blockDim.x + threadIdx.x) >> 5;
    int lane = threadIdx.x & 31;
    if (w >= NN) return;
    unsigned lane4 = (unsigned)lane << 2;
    float ax = 0.f, ay = 0.f;
    op_pair(__ldg(idxes_seq + 2), __ldg(idxes_seq + 3), w, g_s1, lane4, ax, ay);
    op_pair(__ldg(idxes_res + 0), __ldg(idxes_res + 1), w, g_h,  lane4, ax, ay);

    float s  = ax + ay;
    float ss = ax * ax + ay * ay;
    #pragma unroll
    for (int d = 16; d; d >>= 1) {
        s  += __shfl_xor_sync(0xffffffffu, s,  d);
        ss += __shfl_xor_sync(0xffffffffu, ss, d);
    }
    float mu   = s * (1.0f / 64.0f);
    float var  = ss * (1.0f / 64.0f) - mu * mu;
    float rstd = rsqrtf(var + 1e-5f);

    float2 g2 = ((const float2*)gamma)[lane];
    float2 b2 = ((const float2*)beta)[lane];
    float y0 = (ax - mu) * rstd * g2.x + b2.x;
    float y1 = (ay - mu) * rstd * g2.y + b2.y;
    y0 = 0.5f * y0 * (1.0f + erff(y0 * 0.70710678118654752f));
    y1 = 0.5f * y1 * (1.0f + erff(y1 * 0.70710678118654752f));
    ((float2*)out)[(size_t)w * 32 + lane] = make_float2(y0, y1);
}

// ---------------- launch -----------------------------------------------------
extern "C" void kernel_launch(void* const* d_in, const int* in_sizes, int n_in,
                              void* d_out, int out_size) {
    const float* x         = (const float*)d_in[0];
    const float* W         = (const float*)d_in[1];
    const float* b         = (const float*)d_in[2];
    const int*   rows      = (const int*)  d_in[3];
    const int*   cols      = (const int*)  d_in[4];
    const float* vals      = (const float*)d_in[5];
    const float* gamma     = (const float*)d_in[6];
    const float* beta      = (const float*)d_in[7];
    const int*   idxes_seq = (const int*)  d_in[8];
    const int*   idxes_res = (const int*)  d_in[9];
    float*       out       = (float*)d_out;

    zero_cnt_kernel<<<(NADJ * NN + 255) / 256, 256>>>();
    build_gemm_kernel<<<dim3(BUILD_BLKX, NADJ + 1), 256>>>(
        rows, cols, vals, x, W, b, idxes_seq, idxes_res);
    spmm_mid_kernel<<<(NN + 7) / 8, 256>>>(idxes_seq);
    final_kernel<<<(NN + 7) / 8, 256>>>(idxes_seq, idxes_res, gamma, beta, out);
}

// round 10
// speedup vs baseline: 1.1809x; 1.1382x over previous
#include <cuda_runtime.h>
#include <cuda_fp16.h>

#define NN    100000
#define EE    1600000
#define NADJ  4
#define DD    64
#define SLACK 64                      // bucket slots per row; P(deg>64)~1e-19

#define BUILD_BLKX ((EE + 255) / 256) // 6250
#define GEMM_BLKS  ((NN + 63) / 64)   // 1563
#define GATHER_BLKS (NN / 16)         // 2 rows/warp, 8 warps/block -> 6250

// ---------------- device scratch (static globals; no allocs allowed) ------
__device__ __align__(16) __half2 g_h [(size_t)NN * 32];   // s0 (fp16 storage)
__device__ __align__(16) __half2 g_s1[(size_t)NN * 32];   // s1 (fp16 storage)
__device__ __align__(16) float2  g_edges[(size_t)NADJ * NN * SLACK]; // bucketed
__device__ int g_cnt[NADJ * NN];

// used-adjacency predicate (6 cached loads)
__device__ __forceinline__ bool adj_used(int a, const int* __restrict__ iq,
                                         const int* __restrict__ ir) {
    return __ldg(iq + 0) == a || __ldg(iq + 1) == a ||
           __ldg(iq + 2) == a || __ldg(iq + 3) == a ||
           __ldg(ir + 0) == a || __ldg(ir + 1) == a;
}

__global__ void zero_cnt_kernel() {
    int i = blockIdx.x * blockDim.x + threadIdx.x;
    if (i < NADJ * NN) g_cnt[i] = 0;
}

// ---------------- fused bucket-build + GEMM ---------------------------------
__global__ void build_gemm_kernel(const int* __restrict__ rows,
                                  const int* __restrict__ cols,
                                  const float* __restrict__ vals,
                                  const float* __restrict__ x,
                                  const float* __restrict__ Wm,
                                  const float* __restrict__ b,
                                  const int* __restrict__ iq,
                                  const int* __restrict__ ir) {
    __shared__ float4 Ws4[64 * 16];
    __shared__ float  Xs[64 * 65];
    int tid = threadIdx.x;

    if (blockIdx.y < NADJ) {
        int a = blockIdx.y;
        if (!adj_used(a, iq, ir)) return;
        int e = blockIdx.x * blockDim.x + tid;
        if (e < EE) {
            size_t idx = (size_t)a * EE + e;
            int   r = rows[idx];
            int   c = cols[idx];
            float v = vals[idx];
            int   p = atomicAdd(&g_cnt[a * NN + r], 1);
            p = min(p, SLACK - 1);   // structurally unreachable; guards memory
            g_edges[((size_t)a * NN + r) * SLACK + p] =
                make_float2(__int_as_float(c << 7), v);   // byte offset of row
        }
        return;
    }

    // ---- GEMM part ----
    if (blockIdx.x >= GEMM_BLKS) return;
    for (int i = tid; i < 64 * 16; i += 256) Ws4[i] = ((const float4*)Wm)[i];
    int rowBase = blockIdx.x * 64;
    for (int i = tid; i < 1024; i += 256) {
        int r = i >> 4, c4 = i & 15;
        int grow = rowBase + r;
        float4 v = make_float4(0.f, 0.f, 0.f, 0.f);
        if (grow < NN) v = ((const float4*)x)[(size_t)grow * 16 + c4];
        int o = r * 65 + c4 * 4;
        Xs[o] = v.x; Xs[o + 1] = v.y; Xs[o + 2] = v.z; Xs[o + 3] = v.w;
    }
    __syncthreads();
    int tx = tid & 15, ty = tid >> 4;
    float4 a0 = make_float4(0.f,0.f,0.f,0.f), a1 = a0, a2 = a0, a3 = a0;
    #pragma unroll 8
    for (int k = 0; k < 64; k++) {
        float4 wv = Ws4[k * 16 + tx];
        float x0 = Xs[(ty * 4 + 0) * 65 + k];
        float x1 = Xs[(ty * 4 + 1) * 65 + k];
        float x2 = Xs[(ty * 4 + 2) * 65 + k];
        float x3 = Xs[(ty * 4 + 3) * 65 + k];
        a0.x += x0 * wv.x; a0.y += x0 * wv.y; a0.z += x0 * wv.z; a0.w += x0 * wv.w;
        a1.x += x1 * wv.x; a1.y += x1 * wv.y; a1.z += x1 * wv.z; a1.w += x1 * wv.w;
        a2.x += x2 * wv.x; a2.y += x2 * wv.y; a2.z += x2 * wv.z; a2.w += x2 * wv.w;
        a3.x += x3 * wv.x; a3.y += x3 * wv.y; a3.z += x3 * wv.z; a3.w += x3 * wv.w;
    }
    float4 bv = ((const float4*)b)[tx];
    float4 outs[4] = {a0, a1, a2, a3};
    int r0 = rowBase + ty * 4;
    #pragma unroll
    for (int i = 0; i < 4; i++) {
        int r = r0 + i;
        if (r < NN) {
            float4 o = outs[i];
            o.x += bv.x; o.y += bv.y; o.z += bv.z; o.w += bv.w;
            __half2 p0 = __floats2half2_rn(o.x, o.y);
            __half2 p1 = __floats2half2_rn(o.z, o.w);
            __half2 pk[2] = {p0, p1};
            ((uint2*)g_h)[(size_t)r * 16 + tx] = *(uint2*)pk;
        }
    }
}

// ---------------- gather SpMM core: 2 rows per warp -------------------------
// Lanes 0-15 handle row r0=2w (4 cols/lane via LDG.64 of 2 half2), lanes
// 16-31 handle row r1=2w+1. One edge LDG.64 and one h LDG.64 serve 2 edges.
// Loop bound = warp-max of the two list lengths; short half predicated to a
// null edge (offset 0 = in-bounds, val 0 = exact).
__device__ __forceinline__ void accum_dual(int a, int row,
                                           const __half2* __restrict__ src,
                                           unsigned subOff, float4& acc) {
    const float2* __restrict__ ed = g_edges + ((size_t)a * NN + row) * SLACK;
    const char* __restrict__ base = (const char*)src + subOff;
    int end  = min(__ldg(&g_cnt[a * NN + row]), SLACK);
    int wmax = max(end, __shfl_xor_sync(0xffffffffu, end, 16));
    const float2 znull = make_float2(0.f, 0.f);
    for (int i = 0; i < wmax; i += 4) {
        float2 e0 = (i + 0 < end) ? ed[i + 0] : znull;
        float2 e1 = (i + 1 < end) ? ed[i + 1] : znull;
        float2 e2 = (i + 2 < end) ? ed[i + 2] : znull;
        float2 e3 = (i + 3 < end) ? ed[i + 3] : znull;
        uint2 r0 = __ldg((const uint2*)(base + (unsigned)__float_as_int(e0.x)));
        uint2 r1 = __ldg((const uint2*)(base + (unsigned)__float_as_int(e1.x)));
        uint2 r2 = __ldg((const uint2*)(base + (unsigned)__float_as_int(e2.x)));
        uint2 r3 = __ldg((const uint2*)(base + (unsigned)__float_as_int(e3.x)));
        float2 p0 = __half22float2(*(__half2*)&r0.x), q0 = __half22float2(*(__half2*)&r0.y);
        float2 p1 = __half22float2(*(__half2*)&r1.x), q1 = __half22float2(*(__half2*)&r1.y);
        float2 p2 = __half22float2(*(__half2*)&r2.x), q2 = __half22float2(*(__half2*)&r2.y);
        float2 p3 = __half22float2(*(__half2*)&r3.x), q3 = __half22float2(*(__half2*)&r3.y);
        acc.x += e0.y * p0.x; acc.y += e0.y * p0.y; acc.z += e0.y * q0.x; acc.w += e0.y * q0.y;
        acc.x += e1.y * p1.x; acc.y += e1.y * p1.y; acc.z += e1.y * q1.x; acc.w += e1.y * q1.y;
        acc.x += e2.y * p2.x; acc.y += e2.y * p2.y; acc.z += e2.y * q2.x; acc.w += e2.y * q2.y;
        acc.x += e3.y * p3.x; acc.y += e3.y * p3.y; acc.z += e3.y * q3.x; acc.w += e3.y * q3.y;
    }
}

__device__ __forceinline__ float4 op_pair_dual(int a0, int a1, int row,
                                               const __half2* __restrict__ src,
                                               unsigned subOff) {
    float4 acc = make_float4(0.f, 0.f, 0.f, 0.f);
    accum_dual(a0, row, src, subOff, acc);
    if (a0 != a1) {
        accum_dual(a1, row, src, subOff, acc);
        acc.x *= 0.5f; acc.y *= 0.5f; acc.z *= 0.5f; acc.w *= 0.5f;
    }
    return acc;
}

// s1 = op_seq0(h)
__global__ void __launch_bounds__(256, 6)
spmm_mid_kernel(const int* __restrict__ idxes_seq) {
    int gw   = (blockIdx.x * blockDim.x + threadIdx.x) >> 5;   // warp id
    int lane = threadIdx.x & 31;
    int row  = 2 * gw + (lane >> 4);                           // < NN by grid
    int sub  = lane & 15;
    unsigned subOff = (unsigned)sub << 3;                      // sub*8 bytes
    float4 acc = op_pair_dual(__ldg(idxes_seq + 0), __ldg(idxes_seq + 1),
                              row, g_h, subOff);
    __half2 pk[2] = {__floats2half2_rn(acc.x, acc.y),
                     __floats2half2_rn(acc.z, acc.w)};
    ((uint2*)g_s1)[(size_t)row * 16 + sub] = *(uint2*)pk;
}

// s2 = op_seq1(s1) + op_res(h); LN; exact GELU
__global__ void __launch_bounds__(256, 6)
final_kernel(const int* __restrict__ idxes_seq,
             const int* __restrict__ idxes_res,
             const float* __restrict__ gamma,
             const float* __restrict__ beta,
             float* __restrict__ out) {
    int gw   = (blockIdx.x * blockDim.x + threadIdx.x) >> 5;
    int lane = threadIdx.x & 31;
    int row  = 2 * gw + (lane >> 4);
    int sub  = lane & 15;
    unsigned subOff = (unsigned)sub << 3;

    float4 a = op_pair_dual(__ldg(idxes_seq + 2), __ldg(idxes_seq + 3),
                            row, g_s1, subOff);
    float4 b = op_pair_dual(__ldg(idxes_res + 0), __ldg(idxes_res + 1),
                            row, g_h, subOff);
    a.x += b.x; a.y += b.y; a.z += b.z; a.w += b.w;

    // LayerNorm over 64 cols = 16 lanes x 4 vals (within half-warp)
    float s  = a.x + a.y + a.z + a.w;
    float ss = a.x * a.x + a.y * a.y + a.z * a.z + a.w * a.w;
    #pragma unroll
    for (int d = 8; d; d >>= 1) {
        s  += __shfl_xor_sync(0xffffffffu, s,  d);
        ss += __shfl_xor_sync(0xffffffffu, ss, d);
    }
    float mu   = s * (1.0f / 64.0f);
    float var  = ss * (1.0f / 64.0f) - mu * mu;
    float rstd = rsqrtf(var + 1e-5f);

    float4 g4 = ((const float4*)gamma)[sub];
    float4 b4 = ((const float4*)beta)[sub];
    float y0 = (a.x - mu) * rstd * g4.x + b4.x;
    float y1 = (a.y - mu) * rstd * g4.y + b4.y;
    float y2 = (a.z - mu) * rstd * g4.z + b4.z;
    float y3 = (a.w - mu) * rstd * g4.w + b4.w;
    const float k = 0.70710678118654752f;
    y0 = 0.5f * y0 * (1.0f + erff(y0 * k));
    y1 = 0.5f * y1 * (1.0f + erff(y1 * k));
    y2 = 0.5f * y2 * (1.0f + erff(y2 * k));
    y3 = 0.5f * y3 * (1.0f + erff(y3 * k));
    ((float4*)out)[(size_t)row * 16 + sub] = make_float4(y0, y1, y2, y3);
}

// ---------------- launch -----------------------------------------------------
extern "C" void kernel_launch(void* const* d_in, const int* in_sizes, int n_in,
                              void* d_out, int out_size) {
    const float* x         = (const float*)d_in[0];
    const float* W         = (const float*)d_in[1];
    const float* b         = (const float*)d_in[2];
    const int*   rows      = (const int*)  d_in[3];
    const int*   cols      = (const int*)  d_in[4];
    const float* vals      = (const float*)d_in[5];
    const float* gamma     = (const float*)d_in[6];
    const float* beta      = (const float*)d_in[7];
    const int*   idxes_seq = (const int*)  d_in[8];
    const int*   idxes_res = (const int*)  d_in[9];
    float*       out       = (float*)d_out;

    zero_cnt_kernel<<<(NADJ * NN + 255) / 256, 256>>>();
    build_gemm_kernel<<<dim3(BUILD_BLKX, NADJ + 1), 256>>>(
        rows, cols, vals, x, W, b, idxes_seq, idxes_res);
    spmm_mid_kernel<<<GATHER_BLKS, 256>>>(idxes_seq);
    final_kernel<<<GATHER_BLKS, 256>>>(idxes_seq, idxes_res, gamma, beta, out);
}

// round 11
// speedup vs baseline: 1.3099x; 1.1092x over previous
#include <cuda_runtime.h>
#include <cuda_fp16.h>

#define NN    100000
#define EE    1600000
#define NADJ  4
#define DD    64
#define SLACK 64                      // bucket slots per row; P(deg>64)~1e-19

#define BUILD_BLKX ((EE + 255) / 256) // 6250
#define GEMM_BLKS  ((NN + 63) / 64)   // 1563
#define GATHER_BLKS (NN / 16)         // 2 rows/warp, 8 warps/block -> 6250

// ---------------- device scratch (static globals; no allocs allowed) ------
// g_edges: BSS-zeroed. Slots >= cnt are NEVER written; a zero slot decodes as
// (byte-offset 0, val 0.0f) == null edge contributing exactly 0. This lets the
// gather loop run unpredicated to a rounded bound.
__device__ __align__(16) __half2 g_h [(size_t)NN * 32];   // s0 (fp16 storage)
__device__ __align__(16) __half2 g_s1[(size_t)NN * 32];   // s1 (fp16 storage)
__device__ __align__(16) float2  g_edges[(size_t)NADJ * NN * SLACK]; // bucketed
__device__ int g_cnt[NADJ * NN];

// used-adjacency predicate (6 cached loads)
__device__ __forceinline__ bool adj_used(int a, const int* __restrict__ iq,
                                         const int* __restrict__ ir) {
    return __ldg(iq + 0) == a || __ldg(iq + 1) == a ||
           __ldg(iq + 2) == a || __ldg(iq + 3) == a ||
           __ldg(ir + 0) == a || __ldg(ir + 1) == a;
}

__global__ void zero_cnt_kernel() {
    int i = blockIdx.x * blockDim.x + threadIdx.x;
    if (i < NADJ * NN) g_cnt[i] = 0;
}

// ---------------- fused bucket-build + GEMM ---------------------------------
__global__ void build_gemm_kernel(const int* __restrict__ rows,
                                  const int* __restrict__ cols,
                                  const float* __restrict__ vals,
                                  const float* __restrict__ x,
                                  const float* __restrict__ Wm,
                                  const float* __restrict__ b,
                                  const int* __restrict__ iq,
                                  const int* __restrict__ ir) {
    __shared__ float4 Ws4[64 * 16];
    __shared__ float  Xs[64 * 65];
    int tid = threadIdx.x;

    if (blockIdx.y < NADJ) {
        int a = blockIdx.y;
        if (!adj_used(a, iq, ir)) return;
        int e = blockIdx.x * blockDim.x + tid;
        if (e < EE) {
            size_t idx = (size_t)a * EE + e;
            int   r = rows[idx];
            int   c = cols[idx];
            float v = vals[idx];
            int   p = atomicAdd(&g_cnt[a * NN + r], 1);
            p = min(p, SLACK - 1);   // structurally unreachable; guards memory
            g_edges[((size_t)a * NN + r) * SLACK + p] =
                make_float2(__int_as_float(c << 7), v);   // byte offset of row
        }
        return;
    }

    // ---- GEMM part ----
    if (blockIdx.x >= GEMM_BLKS) return;
    for (int i = tid; i < 64 * 16; i += 256) Ws4[i] = ((const float4*)Wm)[i];
    int rowBase = blockIdx.x * 64;
    for (int i = tid; i < 1024; i += 256) {
        int r = i >> 4, c4 = i & 15;
        int grow = rowBase + r;
        float4 v = make_float4(0.f, 0.f, 0.f, 0.f);
        if (grow < NN) v = ((const float4*)x)[(size_t)grow * 16 + c4];
        int o = r * 65 + c4 * 4;
        Xs[o] = v.x; Xs[o + 1] = v.y; Xs[o + 2] = v.z; Xs[o + 3] = v.w;
    }
    __syncthreads();
    int tx = tid & 15, ty = tid >> 4;
    float4 a0 = make_float4(0.f,0.f,0.f,0.f), a1 = a0, a2 = a0, a3 = a0;
    #pragma unroll 8
    for (int k = 0; k < 64; k++) {
        float4 wv = Ws4[k * 16 + tx];
        float x0 = Xs[(ty * 4 + 0) * 65 + k];
        float x1 = Xs[(ty * 4 + 1) * 65 + k];
        float x2 = Xs[(ty * 4 + 2) * 65 + k];
        float x3 = Xs[(ty * 4 + 3) * 65 + k];
        a0.x += x0 * wv.x; a0.y += x0 * wv.y; a0.z += x0 * wv.z; a0.w += x0 * wv.w;
        a1.x += x1 * wv.x; a1.y += x1 * wv.y; a1.z += x1 * wv.z; a1.w += x1 * wv.w;
        a2.x += x2 * wv.x; a2.y += x2 * wv.y; a2.z += x2 * wv.z; a2.w += x2 * wv.w;
        a3.x += x3 * wv.x; a3.y += x3 * wv.y; a3.z += x3 * wv.z; a3.w += x3 * wv.w;
    }
    float4 bv = ((const float4*)b)[tx];
    float4 outs[4] = {a0, a1, a2, a3};
    int r0 = rowBase + ty * 4;
    #pragma unroll
    for (int i = 0; i < 4; i++) {
        int r = r0 + i;
        if (r < NN) {
            float4 o = outs[i];
            o.x += bv.x; o.y += bv.y; o.z += bv.z; o.w += bv.w;
            __half2 p0 = __floats2half2_rn(o.x, o.y);
            __half2 p1 = __floats2half2_rn(o.z, o.w);
            __half2 pk[2] = {p0, p1};
            ((uint2*)g_h)[(size_t)r * 16 + tx] = *(uint2*)pk;
        }
    }
}

// ---------------- gather SpMM core: 2 rows per warp, unpredicated -----------
// Lanes 0-15: row 2w; lanes 16-31: row 2w+1. 4 cols/lane (LDG.64 of 2 half2).
// Loop runs to round_up4(warp-max length); slots beyond a row's count are
// BSS-null edges (offset 0, val 0) -> exact no-ops, no predication needed.
__device__ __forceinline__ void accum_dual(int a, int row,
                                           const __half2* __restrict__ src,
                                           unsigned subOff, float4& acc) {
    const float2* __restrict__ ed = g_edges + ((size_t)a * NN + row) * SLACK;
    const char* __restrict__ base = (const char*)src + subOff;
    int end  = min(__ldg(&g_cnt[a * NN + row]), SLACK);
    int wmax = max(end, __shfl_xor_sync(0xffffffffu, end, 16));
    wmax = (wmax + 3) & ~3;
    for (int i = 0; i < wmax; i += 4) {
        float2 e0 = ed[i + 0];
        float2 e1 = ed[i + 1];
        float2 e2 = ed[i + 2];
        float2 e3 = ed[i + 3];
        uint2 r0 = __ldg((const uint2*)(base + (unsigned)__float_as_int(e0.x)));
        uint2 r1 = __ldg((const uint2*)(base + (unsigned)__float_as_int(e1.x)));
        uint2 r2 = __ldg((const uint2*)(base + (unsigned)__float_as_int(e2.x)));
        uint2 r3 = __ldg((const uint2*)(base + (unsigned)__float_as_int(e3.x)));
        float2 p0 = __half22float2(*(__half2*)&r0.x), q0 = __half22float2(*(__half2*)&r0.y);
        float2 p1 = __half22float2(*(__half2*)&r1.x), q1 = __half22float2(*(__half2*)&r1.y);
        float2 p2 = __half22float2(*(__half2*)&r2.x), q2 = __half22float2(*(__half2*)&r2.y);
        float2 p3 = __half22float2(*(__half2*)&r3.x), q3 = __half22float2(*(__half2*)&r3.y);
        acc.x += e0.y * p0.x; acc.y += e0.y * p0.y; acc.z += e0.y * q0.x; acc.w += e0.y * q0.y;
        acc.x += e1.y * p1.x; acc.y += e1.y * p1.y; acc.z += e1.y * q1.x; acc.w += e1.y * q1.y;
        acc.x += e2.y * p2.x; acc.y += e2.y * p2.y; acc.z += e2.y * q2.x; acc.w += e2.y * q2.y;
        acc.x += e3.y * p3.x; acc.y += e3.y * p3.y; acc.z += e3.y * q3.x; acc.w += e3.y * q3.y;
    }
}

__device__ __forceinline__ float4 op_pair_dual(int a0, int a1, int row,
                                               const __half2* __restrict__ src,
                                               unsigned subOff) {
    float4 acc = make_float4(0.f, 0.f, 0.f, 0.f);
    accum_dual(a0, row, src, subOff, acc);
    if (a0 != a1) {
        accum_dual(a1, row, src, subOff, acc);
        acc.x *= 0.5f; acc.y *= 0.5f; acc.z *= 0.5f; acc.w *= 0.5f;
    }
    return acc;
}

// s1 = op_seq0(h)
__global__ void __launch_bounds__(256, 6)
spmm_mid_kernel(const int* __restrict__ idxes_seq) {
    int gw   = (blockIdx.x * blockDim.x + threadIdx.x) >> 5;   // warp id
    int lane = threadIdx.x & 31;
    int row  = 2 * gw + (lane >> 4);                           // < NN by grid
    int sub  = lane & 15;
    unsigned subOff = (unsigned)sub << 3;                      // sub*8 bytes
    float4 acc = op_pair_dual(__ldg(idxes_seq + 0), __ldg(idxes_seq + 1),
                              row, g_h, subOff);
    __half2 pk[2] = {__floats2half2_rn(acc.x, acc.y),
                     __floats2half2_rn(acc.z, acc.w)};
    ((uint2*)g_s1)[(size_t)row * 16 + sub] = *(uint2*)pk;
}

// s2 = op_seq1(s1) + op_res(h); LN; exact GELU
__global__ void __launch_bounds__(256, 6)
final_kernel(const int* __restrict__ idxes_seq,
             const int* __restrict__ idxes_res,
             const float* __restrict__ gamma,
             const float* __restrict__ beta,
             float* __restrict__ out) {
    int gw   = (blockIdx.x * blockDim.x + threadIdx.x) >> 5;
    int lane = threadIdx.x & 31;
    int row  = 2 * gw + (lane >> 4);
    int sub  = lane & 15;
    unsigned subOff = (unsigned)sub << 3;

    float4 a = op_pair_dual(__ldg(idxes_seq + 2), __ldg(idxes_seq + 3),
                            row, g_s1, subOff);
    float4 b = op_pair_dual(__ldg(idxes_res + 0), __ldg(idxes_res + 1),
                            row, g_h, subOff);
    a.x += b.x; a.y += b.y; a.z += b.z; a.w += b.w;

    // LayerNorm over 64 cols = 16 lanes x 4 vals (within half-warp)
    float s  = a.x + a.y + a.z + a.w;
    float ss = a.x * a.x + a.y * a.y + a.z * a.z + a.w * a.w;
    #pragma unroll
    for (int d = 8; d; d >>= 1) {
        s  += __shfl_xor_sync(0xffffffffu, s,  d);
        ss += __shfl_xor_sync(0xffffffffu, ss, d);
    }
    float mu   = s * (1.0f / 64.0f);
    float var  = ss * (1.0f / 64.0f) - mu * mu;
    float rstd = rsqrtf(var + 1e-5f);

    float4 g4 = ((const float4*)gamma)[sub];
    float4 b4 = ((const float4*)beta)[sub];
    float y0 = (a.x - mu) * rstd * g4.x + b4.x;
    float y1 = (a.y - mu) * rstd * g4.y + b4.y;
    float y2 = (a.z - mu) * rstd * g4.z + b4.z;
    float y3 = (a.w - mu) * rstd * g4.w + b4.w;
    const float k = 0.70710678118654752f;
    y0 = 0.5f * y0 * (1.0f + erff(y0 * k));
    y1 = 0.5f * y1 * (1.0f + erff(y1 * k));
    y2 = 0.5f * y2 * (1.0f + erff(y2 * k));
    y3 = 0.5f * y3 * (1.0f + erff(y3 * k));
    ((float4*)out)[(size_t)row * 16 + sub] = make_float4(y0, y1, y2, y3);
}

// ---------------- launch -----------------------------------------------------
extern "C" void kernel_launch(void* const* d_in, const int* in_sizes, int n_in,
                              void* d_out, int out_size) {
    const float* x         = (const float*)d_in[0];
    const float* W         = (const float*)d_in[1];
    const float* b         = (const float*)d_in[2];
    const int*   rows      = (const int*)  d_in[3];
    const int*   cols      = (const int*)  d_in[4];
    const float* vals      = (const float*)d_in[5];
    const float* gamma     = (const float*)d_in[6];
    const float* beta      = (const float*)d_in[7];
    const int*   idxes_seq = (const int*)  d_in[8];
    const int*   idxes_res = (const int*)  d_in[9];
    float*       out       = (float*)d_out;

    zero_cnt_kernel<<<(NADJ * NN + 255) / 256, 256>>>();
    build_gemm_kernel<<<dim3(BUILD_BLKX, NADJ + 1), 256>>>(
        rows, cols, vals, x, W, b, idxes_seq, idxes_res);
    spmm_mid_kernel<<<GATHER_BLKS, 256>>>(idxes_seq);
    final_kernel<<<GATHER_BLKS, 256>>>(idxes_seq, idxes_res, gamma, beta, out);
}

// round 12
// speedup vs baseline: 1.3261x; 1.0124x over previous
#include <cuda_runtime.h>
#include <cuda_fp16.h>

#define NN    100000
#define EE    1600000
#define NADJ  4
#define DD    64
#define SLACK 64                      // bucket slots per row; P(deg>64)~1e-19

#define BUILD_BLKX ((EE + 255) / 256) // 6250
#define GEMM_BLKS  ((NN + 63) / 64)   // 1563
#define GATHER_BLKS (NN / 16)         // 2 rows/warp, 8 warps/block -> 6250

// ---------------- device scratch (static globals; no allocs allowed) ------
// g_edges: BSS-zeroed. Slots >= cnt are NEVER written; a zero slot decodes as
// (byte-offset 0, val 0.0f) == null edge contributing exactly 0. This lets the
// gather loop run unpredicated to a rounded bound.
__device__ __align__(16) __half2 g_h [(size_t)NN * 32];   // s0 (fp16 storage)
__device__ __align__(16) __half2 g_s1[(size_t)NN * 32];   // s1 (fp16 storage)
__device__ __align__(16) float2  g_edges[(size_t)NADJ * NN * SLACK]; // bucketed
__device__ int g_cnt[NADJ * NN];

// used-adjacency predicate (6 cached loads)
__device__ __forceinline__ bool adj_used(int a, const int* __restrict__ iq,
                                         const int* __restrict__ ir) {
    return __ldg(iq + 0) == a || __ldg(iq + 1) == a ||
           __ldg(iq + 2) == a || __ldg(iq + 3) == a ||
           __ldg(ir + 0) == a || __ldg(ir + 1) == a;
}

__global__ void zero_cnt_kernel() {
    int i = blockIdx.x * blockDim.x + threadIdx.x;
    if (i < NADJ * NN) g_cnt[i] = 0;
}

// ---------------- fused bucket-build + GEMM ---------------------------------
__global__ void build_gemm_kernel(const int* __restrict__ rows,
                                  const int* __restrict__ cols,
                                  const float* __restrict__ vals,
                                  const float* __restrict__ x,
                                  const float* __restrict__ Wm,
                                  const float* __restrict__ b,
                                  const int* __restrict__ iq,
                                  const int* __restrict__ ir) {
    __shared__ float4 Ws4[64 * 16];
    __shared__ float  Xs[64 * 65];
    int tid = threadIdx.x;

    if (blockIdx.y < NADJ) {
        int a = blockIdx.y;
        if (!adj_used(a, iq, ir)) return;
        int e = blockIdx.x * blockDim.x + tid;
        if (e < EE) {
            size_t idx = (size_t)a * EE + e;
            int   r = rows[idx];
            int   c = cols[idx];
            float v = vals[idx];
            int   p = atomicAdd(&g_cnt[a * NN + r], 1);
            p = min(p, SLACK - 1);   // structurally unreachable; guards memory
            g_edges[((size_t)a * NN + r) * SLACK + p] =
                make_float2(__int_as_float(c << 7), v);   // byte offset of row
        }
        return;
    }

    // ---- GEMM part ----
    if (blockIdx.x >= GEMM_BLKS) return;
    for (int i = tid; i < 64 * 16; i += 256) Ws4[i] = ((const float4*)Wm)[i];
    int rowBase = blockIdx.x * 64;
    for (int i = tid; i < 1024; i += 256) {
        int r = i >> 4, c4 = i & 15;
        int grow = rowBase + r;
        float4 v = make_float4(0.f, 0.f, 0.f, 0.f);
        if (grow < NN) v = ((const float4*)x)[(size_t)grow * 16 + c4];
        int o = r * 65 + c4 * 4;
        Xs[o] = v.x; Xs[o + 1] = v.y; Xs[o + 2] = v.z; Xs[o + 3] = v.w;
    }
    __syncthreads();
    int tx = tid & 15, ty = tid >> 4;
    float4 a0 = make_float4(0.f,0.f,0.f,0.f), a1 = a0, a2 = a0, a3 = a0;
    #pragma unroll 8
    for (int k = 0; k < 64; k++) {
        float4 wv = Ws4[k * 16 + tx];
        float x0 = Xs[(ty * 4 + 0) * 65 + k];
        float x1 = Xs[(ty * 4 + 1) * 65 + k];
        float x2 = Xs[(ty * 4 + 2) * 65 + k];
        float x3 = Xs[(ty * 4 + 3) * 65 + k];
        a0.x += x0 * wv.x; a0.y += x0 * wv.y; a0.z += x0 * wv.z; a0.w += x0 * wv.w;
        a1.x += x1 * wv.x; a1.y += x1 * wv.y; a1.z += x1 * wv.z; a1.w += x1 * wv.w;
        a2.x += x2 * wv.x; a2.y += x2 * wv.y; a2.z += x2 * wv.z; a2.w += x2 * wv.w;
        a3.x += x3 * wv.x; a3.y += x3 * wv.y; a3.z += x3 * wv.z; a3.w += x3 * wv.w;
    }
    float4 bv = ((const float4*)b)[tx];
    float4 outs[4] = {a0, a1, a2, a3};
    int r0 = rowBase + ty * 4;
    #pragma unroll
    for (int i = 0; i < 4; i++) {
        int r = r0 + i;
        if (r < NN) {
            float4 o = outs[i];
            o.x += bv.x; o.y += bv.y; o.z += bv.z; o.w += bv.w;
            __half2 p0 = __floats2half2_rn(o.x, o.y);
            __half2 p1 = __floats2half2_rn(o.z, o.w);
            __half2 pk[2] = {p0, p1};
            ((uint2*)g_h)[(size_t)r * 16 + tx] = *(uint2*)pk;
        }
    }
}

// ---------------- gather SpMM core: 2 rows per warp, unpredicated -----------
// Lanes 0-15: row 2w; lanes 16-31: row 2w+1. 4 cols/lane (LDG.64 of 2 half2).
// Loop runs to round_up4(warp-max length); slots beyond a row's count are
// BSS-null edges (offset 0, val 0) -> exact no-ops, no predication needed.
__device__ __forceinline__ void accum_dual(int a, int row,
                                           const __half2* __restrict__ src,
                                           unsigned subOff, float4& acc) {
    const float2* __restrict__ ed = g_edges + ((size_t)a * NN + row) * SLACK;
    const char* __restrict__ base = (const char*)src + subOff;
    int end  = min(__ldg(&g_cnt[a * NN + row]), SLACK);
    int wmax = max(end, __shfl_xor_sync(0xffffffffu, end, 16));
    wmax = (wmax + 3) & ~3;
    for (int i = 0; i < wmax; i += 4) {
        float2 e0 = ed[i + 0];
        float2 e1 = ed[i + 1];
        float2 e2 = ed[i + 2];
        float2 e3 = ed[i + 3];
        uint2 r0 = __ldg((const uint2*)(base + (unsigned)__float_as_int(e0.x)));
        uint2 r1 = __ldg((const uint2*)(base + (unsigned)__float_as_int(e1.x)));
        uint2 r2 = __ldg((const uint2*)(base + (unsigned)__float_as_int(e2.x)));
        uint2 r3 = __ldg((const uint2*)(base + (unsigned)__float_as_int(e3.x)));
        float2 p0 = __half22float2(*(__half2*)&r0.x), q0 = __half22float2(*(__half2*)&r0.y);
        float2 p1 = __half22float2(*(__half2*)&r1.x), q1 = __half22float2(*(__half2*)&r1.y);
        float2 p2 = __half22float2(*(__half2*)&r2.x), q2 = __half22float2(*(__half2*)&r2.y);
        float2 p3 = __half22float2(*(__half2*)&r3.x), q3 = __half22float2(*(__half2*)&r3.y);
        acc.x += e0.y * p0.x; acc.y += e0.y * p0.y; acc.z += e0.y * q0.x; acc.w += e0.y * q0.y;
        acc.x += e1.y * p1.x; acc.y += e1.y * p1.y; acc.z += e1.y * q1.x; acc.w += e1.y * q1.y;
        acc.x += e2.y * p2.x; acc.y += e2.y * p2.y; acc.z += e2.y * q2.x; acc.w += e2.y * q2.y;
        acc.x += e3.y * p3.x; acc.y += e3.y * p3.y; acc.z += e3.y * q3.x; acc.w += e3.y * q3.y;
    }
}

__device__ __forceinline__ float4 op_pair_dual(int a0, int a1, int row,
                                               const __half2* __restrict__ src,
                                               unsigned subOff) {
    float4 acc = make_float4(0.f, 0.f, 0.f, 0.f);
    accum_dual(a0, row, src, subOff, acc);
    if (a0 != a1) {
        accum_dual(a1, row, src, subOff, acc);
        acc.x *= 0.5f; acc.y *= 0.5f; acc.z *= 0.5f; acc.w *= 0.5f;
    }
    return acc;
}

// s1 = op_seq0(h)
__global__ void __launch_bounds__(256, 8)
spmm_mid_kernel(const int* __restrict__ idxes_seq) {
    int gw   = (blockIdx.x * blockDim.x + threadIdx.x) >> 5;   // warp id
    int lane = threadIdx.x & 31;
    int row  = 2 * gw + (lane >> 4);                           // < NN by grid
    int sub  = lane & 15;
    unsigned subOff = (unsigned)sub << 3;                      // sub*8 bytes
    float4 acc = op_pair_dual(__ldg(idxes_seq + 0), __ldg(idxes_seq + 1),
                              row, g_h, subOff);
    __half2 pk[2] = {__floats2half2_rn(acc.x, acc.y),
                     __floats2half2_rn(acc.z, acc.w)};
    ((uint2*)g_s1)[(size_t)row * 16 + sub] = *(uint2*)pk;
}

// s2 = op_seq1(s1) + op_res(h); LN; exact GELU
__global__ void __launch_bounds__(256, 8)
final_kernel(const int* __restrict__ idxes_seq,
             const int* __restrict__ idxes_res,
             const float* __restrict__ gamma,
             const float* __restrict__ beta,
             float* __restrict__ out) {
    int gw   = (blockIdx.x * blockDim.x + threadIdx.x) >> 5;
    int lane = threadIdx.x & 31;
    int row  = 2 * gw + (lane >> 4);
    int sub  = lane & 15;
    unsigned subOff = (unsigned)sub << 3;

    float4 a = op_pair_dual(__ldg(idxes_seq + 2), __ldg(idxes_seq + 3),
                            row, g_s1, subOff);
    float4 b = op_pair_dual(__ldg(idxes_res + 0), __ldg(idxes_res + 1),
                            row, g_h, subOff);
    a.x += b.x; a.y += b.y; a.z += b.z; a.w += b.w;

    // LayerNorm over 64 cols = 16 lanes x 4 vals (within half-warp)
    float s  = a.x + a.y + a.z + a.w;
    float ss = a.x * a.x + a.y * a.y + a.z * a.z + a.w * a.w;
    #pragma unroll
    for (int d = 8; d; d >>= 1) {
        s  += __shfl_xor_sync(0xffffffffu, s,  d);
        ss += __shfl_xor_sync(0xffffffffu, ss, d);
    }
    float mu   = s * (1.0f / 64.0f);
    float var  = ss * (1.0f / 64.0f) - mu * mu;
    float rstd = rsqrtf(var + 1e-5f);

    float4 g4 = ((const float4*)gamma)[sub];
    float4 b4 = ((const float4*)beta)[sub];
    float y0 = (a.x - mu) * rstd * g4.x + b4.x;
    float y1 = (a.y - mu) * rstd * g4.y + b4.y;
    float y2 = (a.z - mu) * rstd * g4.z + b4.z;
    float y3 = (a.w - mu) * rstd * g4.w + b4.w;
    const float k = 0.70710678118654752f;
    y0 = 0.5f * y0 * (1.0f + erff(y0 * k));
    y1 = 0.5f * y1 * (1.0f + erff(y1 * k));
    y2 = 0.5f * y2 * (1.0f + erff(y2 * k));
    y3 = 0.5f * y3 * (1.0f + erff(y3 * k));
    ((float4*)out)[(size_t)row * 16 + sub] = make_float4(y0, y1, y2, y3);
}

// ---------------- launch -----------------------------------------------------
extern "C" void kernel_launch(void* const* d_in, const int* in_sizes, int n_in,
                              void* d_out, int out_size) {
    const float* x         = (const float*)d_in[0];
    const float* W         = (const float*)d_in[1];
    const float* b         = (const float*)d_in[2];
    const int*   rows      = (const int*)  d_in[3];
    const int*   cols      = (const int*)  d_in[4];
    const float* vals      = (const float*)d_in[5];
    const float* gamma     = (const float*)d_in[6];
    const float* beta      = (const float*)d_in[7];
    const int*   idxes_seq = (const int*)  d_in[8];
    const int*   idxes_res = (const int*)  d_in[9];
    float*       out       = (float*)d_out;

    zero_cnt_kernel<<<(NADJ * NN + 255) / 256, 256>>>();
    build_gemm_kernel<<<dim3(BUILD_BLKX, NADJ + 1), 256>>>(
        rows, cols, vals, x, W, b, idxes_seq, idxes_res);
    spmm_mid_kernel<<<GATHER_BLKS, 256>>>(idxes_seq);
    final_kernel<<<GATHER_BLKS, 256>>>(idxes_seq, idxes_res, gamma, beta, out);
}